// round 5
// baseline (speedup 1.0000x reference)
#include <cuda_runtime.h>
#include <cstdint>

// Problem constants (fixed by the dataset)
#define N_NODES 50000
#define N_EDGES 800000
#define IN_C    512
#define HID_C   512
#define OUT_C   256

#define SCAN_BLK 512
#define NB_SCAN  ((N_NODES + SCAN_BLK - 1) / SCAN_BLK)   // 98

// ---------------------------------------------------------------------------
// Scratch: __device__ globals, referenced directly inside kernels.
// ---------------------------------------------------------------------------
__device__ int   g_is64;                            // 1 if edge_index is int64
__device__ int   g_cnt   [N_NODES];
__device__ int   g_fill  [N_NODES];
__device__ int   g_rowptr[N_NODES + 1];
__device__ int   g_blksum[128];                     // NB_SCAN <= 128
__device__ int   g_col   [N_EDGES];
__device__ float g_dinv  [N_NODES];
__device__ float g_Hs1   [(size_t)N_NODES * HID_C]; // dinv[r] * (X @ W1)
__device__ float g_X1    [(size_t)N_NODES * HID_C]; // relu layer-1 output
__device__ float g_Hs2   [(size_t)N_NODES * OUT_C]; // dinv[r] * (X1 @ W2)

// ---------------------------------------------------------------------------
// Edge-index dtype probe. int64 values in [0, 50000) -> every odd 32-bit
// word is 0. For int32 data, 128 odd words all zero is ~impossible.
// ---------------------------------------------------------------------------
__global__ void k_detect(const int* __restrict__ ei32) {
    if (blockIdx.x != 0 || threadIdx.x != 0) return;
    int allzero = 1;
    #pragma unroll 1
    for (int i = 1; i < 256; i += 2) {
        if (ei32[i] != 0) { allzero = 0; break; }
    }
    g_is64 = allzero;
}

// Fetch edge endpoint `e` from array half `which` (0=src, 1=dst), clamped.
__device__ __forceinline__ int edge_at(const void* ei, int e, int which) {
    int v;
    if (g_is64) {
        const long long* p = (const long long*)ei;
        v = (int)p[(size_t)which * N_EDGES + e];
    } else {
        const int* p = (const int*)ei;
        v = p[(size_t)which * N_EDGES + e];
    }
    v = (v < 0) ? 0 : v;
    v = (v >= N_NODES) ? (N_NODES - 1) : v;
    return v;
}

// ---------------------------------------------------------------------------
// CSR build: count -> scan -> fill  (int atomics only)
// ---------------------------------------------------------------------------
__global__ void k_prep() {
    int i = blockIdx.x * blockDim.x + threadIdx.x;
    if (i < N_NODES) { g_cnt[i] = 0; g_fill[i] = 0; }
}

__global__ void k_count(const void* __restrict__ ei) {
    int e = blockIdx.x * blockDim.x + threadIdx.x;
    if (e < N_EDGES) atomicAdd(&g_cnt[edge_at(ei, e, 1)], 1);
}

__global__ void k_dinv() {
    int i = blockIdx.x * blockDim.x + threadIdx.x;
    if (i < N_NODES) g_dinv[i] = rsqrtf(1.0f + (float)g_cnt[i]);  // +1 self loop
}

// per-block exclusive scan of g_cnt into g_rowptr; block totals to g_blksum
__global__ void k_scan1() {
    __shared__ int sh[SCAN_BLK];
    const int t = threadIdx.x;
    const int i = blockIdx.x * SCAN_BLK + t;
    int v = (i < N_NODES) ? g_cnt[i] : 0;
    sh[t] = v;
    __syncthreads();
    #pragma unroll
    for (int off = 1; off < SCAN_BLK; off <<= 1) {
        int x = (t >= off) ? sh[t - off] : 0;
        __syncthreads();
        sh[t] += x;
        __syncthreads();
    }
    if (i < N_NODES) g_rowptr[i] = sh[t] - v;        // exclusive (block-local)
    if (t == SCAN_BLK - 1) g_blksum[blockIdx.x] = sh[t];
}

// scan the 98 block sums (single block)
__global__ void k_scan2() {
    __shared__ int sh[128];
    const int t = threadIdx.x;                        // 128 threads
    int v = (t < NB_SCAN) ? g_blksum[t] : 0;
    sh[t] = v;
    __syncthreads();
    #pragma unroll
    for (int off = 1; off < 128; off <<= 1) {
        int x = (t >= off) ? sh[t - off] : 0;
        __syncthreads();
        sh[t] += x;
        __syncthreads();
    }
    if (t < NB_SCAN) g_blksum[t] = sh[t] - v;         // exclusive offsets
}

__global__ void k_scan3() {
    int i = blockIdx.x * blockDim.x + threadIdx.x;
    if (i < N_NODES) g_rowptr[i] += g_blksum[i / SCAN_BLK];
    if (i == 0) g_rowptr[N_NODES] = N_EDGES;
}

__global__ void k_fill(const void* __restrict__ ei) {
    int e = blockIdx.x * blockDim.x + threadIdx.x;
    if (e >= N_EDGES) return;
    int d = edge_at(ei, e, 1);
    int pos = g_rowptr[d] + atomicAdd(&g_fill[d], 1);
    if (pos >= 0 && pos < N_EDGES) g_col[pos] = edge_at(ei, e, 0);
}

// ---------------------------------------------------------------------------
// SGEMM 128x128x8 fp32. Compile-time shapes per layer. Epilogue scales the
// row by dinv[row]. Layer 1: A = Xin param; Layer 2: A = g_X1 (symbol).
// ---------------------------------------------------------------------------
template <int LAYER>
__global__ __launch_bounds__(256) void k_gemm(const float* __restrict__ Xin,
                                              const float* __restrict__ W)
{
    constexpr int N = (LAYER == 1) ? HID_C : OUT_C;
    constexpr int K = (LAYER == 1) ? IN_C  : HID_C;
    const float* __restrict__ A = (LAYER == 1) ? Xin : (const float*)g_X1;
    float* Hs = (LAYER == 1) ? g_Hs1 : g_Hs2;

    __shared__ float As[8][128];
    __shared__ float Bs[8][128];

    const int tid = threadIdx.x;
    const int bm = blockIdx.x, bn = blockIdx.y;

    const int aRow = tid >> 1;
    const int aCol = (tid & 1) * 4;
    const int bRow = tid >> 5;
    const int bCol = (tid & 31) * 4;

    const int ty = tid >> 4;
    const int tx = tid & 15;

    const int gRowA = bm * 128 + aRow;
    const float* Aptr = A + (size_t)gRowA * K + aCol;
    const float* Bptr = W + (size_t)bRow * N + bn * 128 + bCol;

    float acc[8][8];
    #pragma unroll
    for (int i = 0; i < 8; i++)
        #pragma unroll
        for (int j = 0; j < 8; j++) acc[i][j] = 0.0f;

    for (int k0 = 0; k0 < K; k0 += 8) {
        float4 a4 = make_float4(0.f, 0.f, 0.f, 0.f);
        if (gRowA < N_NODES) a4 = *(const float4*)(Aptr + k0);
        As[aCol + 0][aRow] = a4.x;
        As[aCol + 1][aRow] = a4.y;
        As[aCol + 2][aRow] = a4.z;
        As[aCol + 3][aRow] = a4.w;

        float4 b4 = *(const float4*)(Bptr + (size_t)k0 * N);
        *(float4*)&Bs[bRow][bCol] = b4;

        __syncthreads();

        #pragma unroll
        for (int k = 0; k < 8; k++) {
            float ra[8], rb[8];
            *(float4*)(ra)     = *(const float4*)&As[k][ty * 8];
            *(float4*)(ra + 4) = *(const float4*)&As[k][ty * 8 + 4];
            *(float4*)(rb)     = *(const float4*)&Bs[k][tx * 8];
            *(float4*)(rb + 4) = *(const float4*)&Bs[k][tx * 8 + 4];
            #pragma unroll
            for (int i = 0; i < 8; i++)
                #pragma unroll
                for (int j = 0; j < 8; j++)
                    acc[i][j] += ra[i] * rb[j];
        }
        __syncthreads();
    }

    #pragma unroll
    for (int i = 0; i < 8; i++) {
        const int row = bm * 128 + ty * 8 + i;
        if (row >= N_NODES) continue;
        const float s = g_dinv[row];
        const size_t base = (size_t)row * N + bn * 128 + tx * 8;
        float4 v0 = make_float4(acc[i][0] * s, acc[i][1] * s, acc[i][2] * s, acc[i][3] * s);
        float4 v1 = make_float4(acc[i][4] * s, acc[i][5] * s, acc[i][6] * s, acc[i][7] * s);
        *(float4*)(Hs + base)     = v0;
        *(float4*)(Hs + base + 4) = v1;
    }
}

// ---------------------------------------------------------------------------
// Aggregation (pure gather, no atomics). One block per node.
// acc = Hs[d] (self loop) + sum_{j in row} Hs[col[j]]; then dinv/bias/(relu).
// ---------------------------------------------------------------------------
__global__ __launch_bounds__(128) void k_agg1(const float* __restrict__ bias) {
    const int d = blockIdx.x;
    const int t = threadIdx.x;                         // 128 = HID_C/4
    const float4* base = (const float4*)g_Hs1;
    float4 acc = base[(size_t)d * 128 + t];
    const int beg = g_rowptr[d], end = g_rowptr[d + 1];
    int j = beg;
    for (; j + 1 < end; j += 2) {
        int s0 = g_col[j], s1 = g_col[j + 1];
        float4 v0 = base[(size_t)s0 * 128 + t];
        float4 v1 = base[(size_t)s1 * 128 + t];
        acc.x += v0.x + v1.x; acc.y += v0.y + v1.y;
        acc.z += v0.z + v1.z; acc.w += v0.w + v1.w;
    }
    if (j < end) {
        int s0 = g_col[j];
        float4 v0 = base[(size_t)s0 * 128 + t];
        acc.x += v0.x; acc.y += v0.y; acc.z += v0.z; acc.w += v0.w;
    }
    const float sc = g_dinv[d];
    float4 b = ((const float4*)bias)[t];
    float4 r;
    r.x = fmaxf(acc.x * sc + b.x, 0.f);
    r.y = fmaxf(acc.y * sc + b.y, 0.f);
    r.z = fmaxf(acc.z * sc + b.z, 0.f);
    r.w = fmaxf(acc.w * sc + b.w, 0.f);
    ((float4*)g_X1)[(size_t)d * 128 + t] = r;
}

__global__ __launch_bounds__(64) void k_agg2(const float* __restrict__ bias,
                                             float* __restrict__ out) {
    const int d = blockIdx.x;
    const int t = threadIdx.x;                         // 64 = OUT_C/4
    const float4* base = (const float4*)g_Hs2;
    float4 acc = base[(size_t)d * 64 + t];
    const int beg = g_rowptr[d], end = g_rowptr[d + 1];
    int j = beg;
    for (; j + 1 < end; j += 2) {
        int s0 = g_col[j], s1 = g_col[j + 1];
        float4 v0 = base[(size_t)s0 * 64 + t];
        float4 v1 = base[(size_t)s1 * 64 + t];
        acc.x += v0.x + v1.x; acc.y += v0.y + v1.y;
        acc.z += v0.z + v1.z; acc.w += v0.w + v1.w;
    }
    if (j < end) {
        int s0 = g_col[j];
        float4 v0 = base[(size_t)s0 * 64 + t];
        acc.x += v0.x; acc.y += v0.y; acc.z += v0.z; acc.w += v0.w;
    }
    const float sc = g_dinv[d];
    float4 b = ((const float4*)bias)[t];
    float4 r;
    r.x = acc.x * sc + b.x;
    r.y = acc.y * sc + b.y;
    r.z = acc.z * sc + b.z;
    r.w = acc.w * sc + b.w;
    ((float4*)out)[(size_t)d * 64 + t] = r;
}

// ---------------------------------------------------------------------------
// Launch
// ---------------------------------------------------------------------------
extern "C" void kernel_launch(void* const* d_in, const int* in_sizes, int n_in,
                              void* d_out, int out_size)
{
    const float* x   = (const float*)d_in[0];
    const void*  ei  = d_in[1];                 // [2, E]; int32 or int64 (probed)
    const float* w1  = (const float*)d_in[2];
    const float* b1  = (const float*)d_in[3];
    const float* w2  = (const float*)d_in[4];
    const float* b2  = (const float*)d_in[5];
    float*       out = (float*)d_out;

    // 0) probe edge_index dtype (device-side, deterministic, capturable)
    k_detect<<<1, 32>>>((const int*)ei);

    // 1) CSR build (int atomics only)
    k_prep <<<(N_NODES + 255) / 256, 256>>>();
    k_count<<<(N_EDGES + 255) / 256, 256>>>(ei);
    k_dinv <<<(N_NODES + 255) / 256, 256>>>();
    k_scan1<<<NB_SCAN, SCAN_BLK>>>();
    k_scan2<<<1, 128>>>();
    k_scan3<<<(N_NODES + 255) / 256, 256>>>();
    k_fill <<<(N_EDGES + 255) / 256, 256>>>(ei);

    // 2) Layer 1
    {
        dim3 grid((N_NODES + 127) / 128, HID_C / 128);
        k_gemm<1><<<grid, 256>>>(x, w1);
    }
    k_agg1<<<N_NODES, 128>>>(b1);

    // 3) Layer 2
    {
        dim3 grid((N_NODES + 127) / 128, OUT_C / 128);
        k_gemm<2><<<grid, 256>>>(x /*unused*/, w2);
    }
    k_agg2<<<N_NODES, 64>>>(b2, out);
}

// round 11
// speedup vs baseline: 1.0291x; 1.0291x over previous
#include <cuda_runtime.h>
#include <cstdint>

// Problem constants (fixed by the dataset)
#define N_NODES 50000
#define N_EDGES 800000
#define IN_C    512
#define HID_C   512
#define OUT_C   256

#define SCAN_BLK 512
#define NB_SCAN  ((N_NODES + SCAN_BLK - 1) / SCAN_BLK)   // 98

// ---------------------------------------------------------------------------
// Scratch: __device__ globals, referenced directly inside kernels.
// ---------------------------------------------------------------------------
__device__ int   g_is64;                            // 1 if edge_index is int64
__device__ int   g_cnt   [N_NODES];
__device__ int   g_fill  [N_NODES];
__device__ int   g_rowptr[N_NODES + 1];
__device__ int   g_blksum[128];                     // NB_SCAN <= 128
__device__ int   g_col   [N_EDGES];
__device__ float g_dinv  [N_NODES];
__device__ float g_Hs1   [(size_t)N_NODES * HID_C]; // dinv[r] * (X @ W1)
__device__ float g_X1    [(size_t)N_NODES * HID_C]; // relu layer-1 output
__device__ float g_Hs2   [(size_t)N_NODES * OUT_C]; // dinv[r] * (X1 @ W2)

// ---------------------------------------------------------------------------
// Edge-index dtype probe. int64 values in [0, 50000) -> every odd 32-bit
// word is 0. For int32 data, 128 odd words all zero is ~impossible.
// ---------------------------------------------------------------------------
__global__ void k_detect(const int* __restrict__ ei32) {
    if (blockIdx.x != 0 || threadIdx.x != 0) return;
    int allzero = 1;
    #pragma unroll 1
    for (int i = 1; i < 256; i += 2) {
        if (ei32[i] != 0) { allzero = 0; break; }
    }
    g_is64 = allzero;
}

// Fetch edge endpoint `e` from array half `which` (0=src, 1=dst), clamped.
__device__ __forceinline__ int edge_at(const void* ei, int e, int which) {
    int v;
    if (g_is64) {
        const long long* p = (const long long*)ei;
        v = (int)p[(size_t)which * N_EDGES + e];
    } else {
        const int* p = (const int*)ei;
        v = p[(size_t)which * N_EDGES + e];
    }
    v = (v < 0) ? 0 : v;
    v = (v >= N_NODES) ? (N_NODES - 1) : v;
    return v;
}

// ---------------------------------------------------------------------------
// CSR build: count -> scan -> fill  (int atomics only)
// ---------------------------------------------------------------------------
__global__ void k_prep() {
    int i = blockIdx.x * blockDim.x + threadIdx.x;
    if (i < N_NODES) { g_cnt[i] = 0; g_fill[i] = 0; }
}

__global__ void k_count(const void* __restrict__ ei) {
    int e = blockIdx.x * blockDim.x + threadIdx.x;
    if (e < N_EDGES) atomicAdd(&g_cnt[edge_at(ei, e, 1)], 1);
}

__global__ void k_dinv() {
    int i = blockIdx.x * blockDim.x + threadIdx.x;
    if (i < N_NODES) g_dinv[i] = rsqrtf(1.0f + (float)g_cnt[i]);  // +1 self loop
}

// per-block exclusive scan of g_cnt into g_rowptr; block totals to g_blksum
__global__ void k_scan1() {
    __shared__ int sh[SCAN_BLK];
    const int t = threadIdx.x;
    const int i = blockIdx.x * SCAN_BLK + t;
    int v = (i < N_NODES) ? g_cnt[i] : 0;
    sh[t] = v;
    __syncthreads();
    #pragma unroll
    for (int off = 1; off < SCAN_BLK; off <<= 1) {
        int x = (t >= off) ? sh[t - off] : 0;
        __syncthreads();
        sh[t] += x;
        __syncthreads();
    }
    if (i < N_NODES) g_rowptr[i] = sh[t] - v;        // exclusive (block-local)
    if (t == SCAN_BLK - 1) g_blksum[blockIdx.x] = sh[t];
}

// scan the 98 block sums (single block)
__global__ void k_scan2() {
    __shared__ int sh[128];
    const int t = threadIdx.x;                        // 128 threads
    int v = (t < NB_SCAN) ? g_blksum[t] : 0;
    sh[t] = v;
    __syncthreads();
    #pragma unroll
    for (int off = 1; off < 128; off <<= 1) {
        int x = (t >= off) ? sh[t - off] : 0;
        __syncthreads();
        sh[t] += x;
        __syncthreads();
    }
    if (t < NB_SCAN) g_blksum[t] = sh[t] - v;         // exclusive offsets
}

__global__ void k_scan3() {
    int i = blockIdx.x * blockDim.x + threadIdx.x;
    if (i < N_NODES) g_rowptr[i] += g_blksum[i / SCAN_BLK];
    if (i == 0) g_rowptr[N_NODES] = N_EDGES;
}

__global__ void k_fill(const void* __restrict__ ei) {
    int e = blockIdx.x * blockDim.x + threadIdx.x;
    if (e >= N_EDGES) return;
    int d = edge_at(ei, e, 1);
    int pos = g_rowptr[d] + atomicAdd(&g_fill[d], 1);
    if (pos >= 0 && pos < N_EDGES) g_col[pos] = edge_at(ei, e, 0);
}

// ---------------------------------------------------------------------------
// SGEMM 128x128x8 fp32 with PACKED f32x2 FMA (Blackwell sm_100 base feature,
// PTX ISA 8.6). Same tiling/staging as the round-5 passing kernel; inner
// product issues fma.rn.f32x2 -> 2 fp32 MACs per instruction.
// Epilogue scales the row by dinv[row].
// ---------------------------------------------------------------------------
#define FMA_X2(acc, a2, b2) \
    asm("fma.rn.f32x2 %0, %1, %2, %0;" : "+l"(acc) : "l"(a2), "l"(b2))
#define PACK_AA(out, abits) \
    asm("mov.b64 %0, {%1, %1};" : "=l"(out) : "r"(abits))
#define UNPACK2(lo, hi, in) \
    asm("mov.b64 {%0, %1}, %2;" : "=r"(lo), "=r"(hi) : "l"(in))

template <int LAYER>
__global__ __launch_bounds__(256) void k_gemm(const float* __restrict__ Xin,
                                              const float* __restrict__ W)
{
    constexpr int N = (LAYER == 1) ? HID_C : OUT_C;
    constexpr int K = (LAYER == 1) ? IN_C  : HID_C;
    const float* __restrict__ A = (LAYER == 1) ? Xin : (const float*)g_X1;
    float* Hs = (LAYER == 1) ? g_Hs1 : g_Hs2;

    __shared__ float As[8][128];
    __shared__ float Bs[8][128];

    const int tid = threadIdx.x;
    const int bm = blockIdx.x, bn = blockIdx.y;

    const int aRow = tid >> 1;
    const int aCol = (tid & 1) * 4;
    const int bRow = tid >> 5;
    const int bCol = (tid & 31) * 4;

    const int ty = tid >> 4;
    const int tx = tid & 15;

    const int gRowA = bm * 128 + aRow;
    const float* Aptr = A + (size_t)gRowA * K + aCol;
    const float* Bptr = W + (size_t)bRow * N + bn * 128 + bCol;

    // 8 rows x 4 column-pairs of f32x2 accumulators (64 x 64-bit regs? no:
    // 32 x 64-bit = 64 x 32-bit regs, same budget as round-5 acc[8][8]).
    unsigned long long acc[8][4];
    #pragma unroll
    for (int i = 0; i < 8; i++)
        #pragma unroll
        for (int j = 0; j < 4; j++) acc[i][j] = 0ull;   // {+0.f, +0.f}

    for (int k0 = 0; k0 < K; k0 += 8) {
        float4 a4 = make_float4(0.f, 0.f, 0.f, 0.f);
        if (gRowA < N_NODES) a4 = *(const float4*)(Aptr + k0);
        As[aCol + 0][aRow] = a4.x;
        As[aCol + 1][aRow] = a4.y;
        As[aCol + 2][aRow] = a4.z;
        As[aCol + 3][aRow] = a4.w;

        float4 b4 = *(const float4*)(Bptr + (size_t)k0 * N);
        *(float4*)&Bs[bRow][bCol] = b4;

        __syncthreads();

        #pragma unroll
        for (int k = 0; k < 8; k++) {
            float ra[8];
            *(float4*)(ra)     = *(const float4*)&As[k][ty * 8];
            *(float4*)(ra + 4) = *(const float4*)&As[k][ty * 8 + 4];
            // B column pairs, loaded directly as 64-bit f32x2 values
            ulonglong2 p0 = *(const ulonglong2*)&Bs[k][tx * 8];
            ulonglong2 p1 = *(const ulonglong2*)&Bs[k][tx * 8 + 4];
            #pragma unroll
            for (int i = 0; i < 8; i++) {
                unsigned long long ai;
                PACK_AA(ai, __float_as_uint(ra[i]));
                FMA_X2(acc[i][0], ai, p0.x);
                FMA_X2(acc[i][1], ai, p0.y);
                FMA_X2(acc[i][2], ai, p1.x);
                FMA_X2(acc[i][3], ai, p1.y);
            }
        }
        __syncthreads();
    }

    // Epilogue: unpack, scale by dinv[row], store
    #pragma unroll
    for (int i = 0; i < 8; i++) {
        const int row = bm * 128 + ty * 8 + i;
        if (row >= N_NODES) continue;
        const float s = g_dinv[row];
        const size_t base = (size_t)row * N + bn * 128 + tx * 8;
        uint32_t u0, u1, u2, u3;
        UNPACK2(u0, u1, acc[i][0]);
        UNPACK2(u2, u3, acc[i][1]);
        float4 v0 = make_float4(__uint_as_float(u0) * s, __uint_as_float(u1) * s,
                                __uint_as_float(u2) * s, __uint_as_float(u3) * s);
        UNPACK2(u0, u1, acc[i][2]);
        UNPACK2(u2, u3, acc[i][3]);
        float4 v1 = make_float4(__uint_as_float(u0) * s, __uint_as_float(u1) * s,
                                __uint_as_float(u2) * s, __uint_as_float(u3) * s);
        *(float4*)(Hs + base)     = v0;
        *(float4*)(Hs + base + 4) = v1;
    }
}

// ---------------------------------------------------------------------------
// Aggregation (pure gather, no atomics). One block per node.
// acc = Hs[d] (self loop) + sum_{j in row} Hs[col[j]]; then dinv/bias/(relu).
// ---------------------------------------------------------------------------
__global__ __launch_bounds__(128) void k_agg1(const float* __restrict__ bias) {
    const int d = blockIdx.x;
    const int t = threadIdx.x;                         // 128 = HID_C/4
    const float4* base = (const float4*)g_Hs1;
    float4 acc = base[(size_t)d * 128 + t];
    const int beg = g_rowptr[d], end = g_rowptr[d + 1];
    int j = beg;
    for (; j + 1 < end; j += 2) {
        int s0 = g_col[j], s1 = g_col[j + 1];
        float4 v0 = base[(size_t)s0 * 128 + t];
        float4 v1 = base[(size_t)s1 * 128 + t];
        acc.x += v0.x + v1.x; acc.y += v0.y + v1.y;
        acc.z += v0.z + v1.z; acc.w += v0.w + v1.w;
    }
    if (j < end) {
        int s0 = g_col[j];
        float4 v0 = base[(size_t)s0 * 128 + t];
        acc.x += v0.x; acc.y += v0.y; acc.z += v0.z; acc.w += v0.w;
    }
    const float sc = g_dinv[d];
    float4 b = ((const float4*)bias)[t];
    float4 r;
    r.x = fmaxf(acc.x * sc + b.x, 0.f);
    r.y = fmaxf(acc.y * sc + b.y, 0.f);
    r.z = fmaxf(acc.z * sc + b.z, 0.f);
    r.w = fmaxf(acc.w * sc + b.w, 0.f);
    ((float4*)g_X1)[(size_t)d * 128 + t] = r;
}

__global__ __launch_bounds__(64) void k_agg2(const float* __restrict__ bias,
                                             float* __restrict__ out) {
    const int d = blockIdx.x;
    const int t = threadIdx.x;                         // 64 = OUT_C/4
    const float4* base = (const float4*)g_Hs2;
    float4 acc = base[(size_t)d * 64 + t];
    const int beg = g_rowptr[d], end = g_rowptr[d + 1];
    int j = beg;
    for (; j + 1 < end; j += 2) {
        int s0 = g_col[j], s1 = g_col[j + 1];
        float4 v0 = base[(size_t)s0 * 64 + t];
        float4 v1 = base[(size_t)s1 * 64 + t];
        acc.x += v0.x + v1.x; acc.y += v0.y + v1.y;
        acc.z += v0.z + v1.z; acc.w += v0.w + v1.w;
    }
    if (j < end) {
        int s0 = g_col[j];
        float4 v0 = base[(size_t)s0 * 64 + t];
        acc.x += v0.x; acc.y += v0.y; acc.z += v0.z; acc.w += v0.w;
    }
    const float sc = g_dinv[d];
    float4 b = ((const float4*)bias)[t];
    float4 r;
    r.x = acc.x * sc + b.x;
    r.y = acc.y * sc + b.y;
    r.z = acc.z * sc + b.z;
    r.w = acc.w * sc + b.w;
    ((float4*)out)[(size_t)d * 64 + t] = r;
}

// ---------------------------------------------------------------------------
// Launch
// ---------------------------------------------------------------------------
extern "C" void kernel_launch(void* const* d_in, const int* in_sizes, int n_in,
                              void* d_out, int out_size)
{
    const float* x   = (const float*)d_in[0];
    const void*  ei  = d_in[1];                 // [2, E]; int32 or int64 (probed)
    const float* w1  = (const float*)d_in[2];
    const float* b1  = (const float*)d_in[3];
    const float* w2  = (const float*)d_in[4];
    const float* b2  = (const float*)d_in[5];
    float*       out = (float*)d_out;

    // 0) probe edge_index dtype (device-side, deterministic, capturable)
    k_detect<<<1, 32>>>((const int*)ei);

    // 1) CSR build (int atomics only)
    k_prep <<<(N_NODES + 255) / 256, 256>>>();
    k_count<<<(N_EDGES + 255) / 256, 256>>>(ei);
    k_dinv <<<(N_NODES + 255) / 256, 256>>>();
    k_scan1<<<NB_SCAN, SCAN_BLK>>>();
    k_scan2<<<1, 128>>>();
    k_scan3<<<(N_NODES + 255) / 256, 256>>>();
    k_fill <<<(N_EDGES + 255) / 256, 256>>>(ei);

    // 2) Layer 1
    {
        dim3 grid((N_NODES + 127) / 128, HID_C / 128);
        k_gemm<1><<<grid, 256>>>(x, w1);
    }
    k_agg1<<<N_NODES, 128>>>(b1);

    // 3) Layer 2
    {
        dim3 grid((N_NODES + 127) / 128, OUT_C / 128);
        k_gemm<2><<<grid, 256>>>(x /*unused*/, w2);
    }
    k_agg2<<<N_NODES, 64>>>(b2, out);
}